// round 2
// baseline (speedup 1.0000x reference)
#include <cuda_runtime.h>
#include <math_constants.h>

// Problem: input (512, 2048, 7, 7) fp32 -> per row of 49: mean of top-4.
// Output: (512, 2048, 1, 1) = 1,048,576 floats.
//
// Strategy: 128 rows per block. Stage 128*49 floats into smem with fully
// coalesced float4 loads (block base is 25088 B -> 16B aligned), then each
// thread scans its own row from smem (stride 49 ~ conflict-free: gcd(49,32)=1)
// maintaining a sorted top-4 in registers with a 7-op branchless update.

#define ROWS_PER_BLOCK 128
#define ROW_LEN 49
#define FLOATS_PER_BLOCK (ROWS_PER_BLOCK * ROW_LEN)   // 6272
#define VEC4_PER_BLOCK   (FLOATS_PER_BLOCK / 4)       // 1568

__global__ __launch_bounds__(ROWS_PER_BLOCK)
void apool_topk4_kernel(const float* __restrict__ in, float* __restrict__ out) {
    __shared__ float s[FLOATS_PER_BLOCK];

    const int tid = threadIdx.x;
    const long long blk_base = (long long)blockIdx.x * FLOATS_PER_BLOCK;

    // ---- Stage: coalesced float4 GMEM -> SMEM ----
    const float4* __restrict__ in4 = reinterpret_cast<const float4*>(in + blk_base);
    float4* s4 = reinterpret_cast<float4*>(s);
    #pragma unroll
    for (int i = tid; i < VEC4_PER_BLOCK; i += ROWS_PER_BLOCK) {
        s4[i] = in4[i];
    }
    __syncthreads();

    // ---- Per-thread streaming top-4 over its row ----
    const float* row = s + tid * ROW_LEN;

    float t0 = -CUDART_INF_F, t1 = -CUDART_INF_F;
    float t2 = -CUDART_INF_F, t3 = -CUDART_INF_F;

    #pragma unroll
    for (int i = 0; i < ROW_LEN; i++) {
        float v = row[i];
        // candidate enters slot 3 if larger than current 4th-largest
        t3 = fmaxf(t3, v);
        // bubble t3 up to restore t0 >= t1 >= t2 >= t3
        float a = fmaxf(t2, t3);
        t3 = fminf(t2, t3);
        float b = fmaxf(t1, a);
        t2 = fminf(t1, a);
        float c = fmaxf(t0, b);
        t1 = fminf(t0, b);
        t0 = c;
    }

    out[(long long)blockIdx.x * ROWS_PER_BLOCK + tid] = (t0 + t1 + t2 + t3) * 0.25f;
}

extern "C" void kernel_launch(void* const* d_in, const int* in_sizes, int n_in,
                              void* d_out, int out_size) {
    const float* in = (const float*)d_in[0];
    float* out = (float*)d_out;
    // out_size = 512*2048 = 1,048,576 rows; 128 rows per block
    int rows = out_size;
    int blocks = rows / ROWS_PER_BLOCK;   // 8192, divides exactly
    apool_topk4_kernel<<<blocks, ROWS_PER_BLOCK>>>(in, out);
}

// round 3
// speedup vs baseline: 1.0695x; 1.0695x over previous
#include <cuda_runtime.h>
#include <math_constants.h>

// Problem: input (512, 2048, 7, 7) fp32 -> per row of 49: mean of top-4.
// Output: (512, 2048, 1, 1) = 1,048,576 floats.
//
// R2: replace 7-op/elem streaming top-4 (serial chain ~16cyc/elem) with
// chunk-of-4 sorting network + bitonic top-4 merge:
//   - sort4: 5 compare-exchange = 10 ops per 4 elems (independent of acc -> ILP)
//   - merge sorted acc (desc) with sorted chunk (desc): max-half of the
//     bitonic sequence (t0..t3, c3..c0) = {max(t_i, c_{3-i})} contains the
//     top-4 and is itself bitonic -> 4 max + 4-CE bitonic resort = 12 ops.
// 259 alu ops/row vs 343, and ~5x shorter dependency chain.

#define ROWS_PER_BLOCK 128
#define ROW_LEN 49
#define FLOATS_PER_BLOCK (ROWS_PER_BLOCK * ROW_LEN)   // 6272
#define VEC4_PER_BLOCK   (FLOATS_PER_BLOCK / 4)       // 1568

__device__ __forceinline__ void ce(float& x, float& y) {
    float hi = fmaxf(x, y);
    float lo = fminf(x, y);
    x = hi; y = lo;
}

// descending sort of 4, 5-CE network
__device__ __forceinline__ void sort4(float& a, float& b, float& c, float& d) {
    ce(a, b); ce(c, d); ce(a, c); ce(b, d); ce(b, c);
}

__global__ __launch_bounds__(ROWS_PER_BLOCK)
void apool_topk4_kernel(const float* __restrict__ in, float* __restrict__ out) {
    __shared__ float s[FLOATS_PER_BLOCK];

    const int tid = threadIdx.x;
    const long long blk_base = (long long)blockIdx.x * FLOATS_PER_BLOCK;

    // ---- Stage: coalesced float4 GMEM -> SMEM ----
    const float4* __restrict__ in4 = reinterpret_cast<const float4*>(in + blk_base);
    float4* s4 = reinterpret_cast<float4*>(s);
    #pragma unroll
    for (int i = tid; i < VEC4_PER_BLOCK; i += ROWS_PER_BLOCK) {
        s4[i] = in4[i];
    }
    __syncthreads();

    // ---- Per-thread top-4 over its row (stride-49 smem: conflict-free) ----
    const float* row = s + tid * ROW_LEN;

    // accumulator = sorted first chunk
    float t0 = row[0], t1 = row[1], t2 = row[2], t3 = row[3];
    sort4(t0, t1, t2, t3);

    #pragma unroll
    for (int k = 1; k < 12; k++) {
        float c0 = row[4 * k + 0];
        float c1 = row[4 * k + 1];
        float c2 = row[4 * k + 2];
        float c3 = row[4 * k + 3];
        sort4(c0, c1, c2, c3);
        // bitonic split: max-half of (t0..t3, c3..c0)
        float m0 = fmaxf(t0, c3);
        float m1 = fmaxf(t1, c2);
        float m2 = fmaxf(t2, c1);
        float m3 = fmaxf(t3, c0);
        // bitonic resort of 4
        ce(m0, m2); ce(m1, m3); ce(m0, m1); ce(m2, m3);
        t0 = m0; t1 = m1; t2 = m2; t3 = m3;
    }

    // last element (index 48): single insert, bubble
    float e = row[48];
    t3 = fmaxf(t3, e);
    ce(t2, t3); ce(t1, t2); ce(t0, t1);

    out[(long long)blockIdx.x * ROWS_PER_BLOCK + tid] = (t0 + t1 + t2 + t3) * 0.25f;
}

extern "C" void kernel_launch(void* const* d_in, const int* in_sizes, int n_in,
                              void* d_out, int out_size) {
    const float* in = (const float*)d_in[0];
    float* out = (float*)d_out;
    int rows = out_size;                       // 1,048,576
    int blocks = rows / ROWS_PER_BLOCK;        // 8192, divides exactly
    apool_topk4_kernel<<<blocks, ROWS_PER_BLOCK>>>(in, out);
}

// round 4
// speedup vs baseline: 1.2260x; 1.1464x over previous
#include <cuda_runtime.h>
#include <cstdint>

// Problem: input (512, 2048, 7, 7) fp32 -> per row of 49: mean of top-4.
// Output: (512, 2048, 1, 1) = 1,048,576 floats.
//
// R3: persistent double-buffered cp.async pipeline. 304 blocks (~2/SM),
// 256 threads, tile = 256 rows (50,176 B). While computing tile k from
// buffer b, the bulk copy of tile k+1 streams into buffer b^1 via
// cp.async.cg (no register staging), keeping DRAM busy through the
// compute phase. Top-4 per row via sort4 + bitonic merge (as R2).

#define THREADS      256
#define TILE_ROWS    256
#define ROW_LEN      49
#define TILE_FLOATS  (TILE_ROWS * ROW_LEN)   // 12544
#define TILE_VEC4    (TILE_FLOATS / 4)       // 3136
#define TILE_BYTES   (TILE_FLOATS * 4)       // 50176
#define GRID_BLOCKS  304

__device__ __forceinline__ void ce(float& x, float& y) {
    float hi = fmaxf(x, y);
    float lo = fminf(x, y);
    x = hi; y = lo;
}

__device__ __forceinline__ void sort4(float& a, float& b, float& c, float& d) {
    ce(a, b); ce(c, d); ce(a, c); ce(b, d); ce(b, c);
}

__device__ __forceinline__ void cp_async16(uint32_t smem_dst, const float4* gmem_src) {
    asm volatile("cp.async.cg.shared.global [%0], [%1], 16;\n"
                 :: "r"(smem_dst), "l"(gmem_src));
}

__device__ __forceinline__ void cp_commit() {
    asm volatile("cp.async.commit_group;\n" ::: "memory");
}

template <int N>
__device__ __forceinline__ void cp_wait() {
    asm volatile("cp.async.wait_group %0;\n" :: "n"(N) : "memory");
}

__global__ __launch_bounds__(THREADS)
void apool_topk4_kernel(const float* __restrict__ in, float* __restrict__ out,
                        int ntiles) {
    extern __shared__ float s[];   // 2 * TILE_FLOATS

    const int tid = threadIdx.x;
    const uint32_t s_base = (uint32_t)__cvta_generic_to_shared(s);

    // ---- Prologue: start loading first tile into buffer 0 ----
    int t = blockIdx.x;
    if (t < ntiles) {
        const float4* src = reinterpret_cast<const float4*>(in) +
                            (long long)t * TILE_VEC4;
        #pragma unroll 4
        for (int i = tid; i < TILE_VEC4; i += THREADS)
            cp_async16(s_base + (uint32_t)i * 16u, src + i);
    }
    cp_commit();

    int buf = 0;
    for (; t < ntiles; t += GRID_BLOCKS) {
        const int tn = t + GRID_BLOCKS;
        if (tn < ntiles) {
            // kick off next tile into the other buffer
            const uint32_t dst = s_base + (uint32_t)(buf ^ 1) * (uint32_t)TILE_BYTES;
            const float4* src = reinterpret_cast<const float4*>(in) +
                                (long long)tn * TILE_VEC4;
            #pragma unroll 4
            for (int i = tid; i < TILE_VEC4; i += THREADS)
                cp_async16(dst + (uint32_t)i * 16u, src + i);
            cp_commit();
            cp_wait<1>();   // current tile's group complete, next stays in flight
        } else {
            cp_commit();
            cp_wait<0>();
        }
        __syncthreads();

        // ---- Compute: one row per thread (stride 49 -> conflict-free) ----
        const float* row = s + buf * TILE_FLOATS + tid * ROW_LEN;

        float t0 = row[0], t1 = row[1], t2 = row[2], t3 = row[3];
        sort4(t0, t1, t2, t3);

        #pragma unroll
        for (int k = 1; k < 12; k++) {
            float c0 = row[4 * k + 0];
            float c1 = row[4 * k + 1];
            float c2 = row[4 * k + 2];
            float c3 = row[4 * k + 3];
            sort4(c0, c1, c2, c3);
            float m0 = fmaxf(t0, c3);
            float m1 = fmaxf(t1, c2);
            float m2 = fmaxf(t2, c1);
            float m3 = fmaxf(t3, c0);
            ce(m0, m2); ce(m1, m3); ce(m0, m1); ce(m2, m3);
            t0 = m0; t1 = m1; t2 = m2; t3 = m3;
        }
        float e = row[48];
        t3 = fmaxf(t3, e);
        ce(t2, t3); ce(t1, t2); ce(t0, t1);

        out[(long long)t * TILE_ROWS + tid] = (t0 + t1 + t2 + t3) * 0.25f;

        buf ^= 1;
        __syncthreads();   // all threads done reading old buffer before next overwrite
    }
}

extern "C" void kernel_launch(void* const* d_in, const int* in_sizes, int n_in,
                              void* d_out, int out_size) {
    const float* in = (const float*)d_in[0];
    float* out = (float*)d_out;

    const int rows = out_size;                 // 1,048,576
    const int ntiles = rows / TILE_ROWS;       // 4096, divides exactly
    const int smem = 2 * TILE_BYTES;           // 100,352 B

    cudaFuncSetAttribute(apool_topk4_kernel,
                         cudaFuncAttributeMaxDynamicSharedMemorySize, smem);
    apool_topk4_kernel<<<GRID_BLOCKS, THREADS, smem>>>(in, out, ntiles);
}